// round 3
// baseline (speedup 1.0000x reference)
#include <cuda_runtime.h>

#define T_DATA 20000
#define E_NO   2000
#define I_NO   500
#define SUB    12
#define CTAP   48            // kernel tail beyond lag 48 is < 1e-6 absolute
#define TT     160           // outputs per fused block (8 warps x 20)
#define SLEN   176           // syn smem row length (j in [0,173) used)
#define INP    224           // IN smem row length (220 used, padded)

// ---------------- device scratch (static, no allocation) ----------------
__device__ unsigned g_mask_e[SUB][64];   // [s][it*4+c], bit l <-> element it*128 + l*4 + c
__device__ unsigned g_mask_i[SUB][16];
__device__ float g_INe[SUB][T_DATA];
__device__ float g_INi[SUB][T_DATA];

// ---------------- K0: pack connectivity into bitmasks (1 warp / word) ----------------
__global__ __launch_bounds__(256) void k_pack(const float* __restrict__ Ce,
                                              const float* __restrict__ Ci) {
    int gt = blockIdx.x * blockDim.x + threadIdx.x;
    int w = gt >> 5, lane = gt & 31;
    if (w < SUB * 64) {
        int s = w >> 6, m = w & 63;
        int it = m >> 2, c = m & 3;
        int e = it * 128 + lane * 4 + c;
        bool b = (e < E_NO) && (Ce[s * E_NO + e] != 0.f);
        unsigned bits = __ballot_sync(0xffffffffu, b);
        if (lane == 0) g_mask_e[s][m] = bits;
    } else if (w < SUB * 64 + SUB * 16) {
        int j = w - SUB * 64;
        int s = j >> 4, m = j & 15;
        int it = m >> 2, c = m & 3;
        int e = it * 128 + lane * 4 + c;
        bool b = (e < I_NO) && (Ci[s * I_NO + e] != 0.f);
        unsigned bits = __ballot_sync(0xffffffffu, b);
        if (lane == 0) g_mask_i[s][m] = bits;
    }
}

// ---------------- K1: IN = S @ C.T via ballot + 64-bit popcount (HBM-bound) --------
__global__ __launch_bounds__(256) void k_reduce(const float* __restrict__ Se,
                                                const float* __restrict__ Si) {
    __shared__ unsigned long long sme2[32][13];  // pair p = words (2p, 2p+1)
    __shared__ unsigned long long smi2[8][13];
    for (int i = threadIdx.x; i < SUB * 32; i += blockDim.x) {
        int s = i >> 5, p = i & 31;
        sme2[p][s] = (unsigned long long)g_mask_e[s][2 * p] |
                     ((unsigned long long)g_mask_e[s][2 * p + 1] << 32);
    }
    for (int i = threadIdx.x; i < SUB * 8; i += blockDim.x) {
        int s = i >> 3, p = i & 7;
        smi2[p][s] = (unsigned long long)g_mask_i[s][2 * p] |
                     ((unsigned long long)g_mask_i[s][2 * p + 1] << 32);
    }
    __syncthreads();

    int warp = threadIdx.x >> 5, lane = threadIdx.x & 31;
    int row = blockIdx.x * 8 + warp;
    if (row >= T_DATA) return;

    const float* re = Se + (size_t)row * E_NO;
    const float* ri = Si + (size_t)row * I_NO;
    int acc_e = 0, acc_i = 0;

#pragma unroll
    for (int ob = 0; ob < 4; ob++) {
        float4 v[4];
#pragma unroll
        for (int q = 0; q < 4; q++) {
            int base = (ob * 4 + q) * 128 + lane * 4;
            v[q] = (base < E_NO) ? *(const float4*)(re + base)
                                 : make_float4(0.f, 0.f, 0.f, 0.f);
        }
#pragma unroll
        for (int q = 0; q < 4; q++) {
            int it = ob * 4 + q;
            unsigned m0 = __ballot_sync(0xffffffffu, v[q].x != 0.f);
            unsigned m1 = __ballot_sync(0xffffffffu, v[q].y != 0.f);
            unsigned m2 = __ballot_sync(0xffffffffu, v[q].z != 0.f);
            unsigned m3 = __ballot_sync(0xffffffffu, v[q].w != 0.f);
            if (lane < SUB) {
                unsigned long long A = (unsigned long long)m0 | ((unsigned long long)m1 << 32);
                unsigned long long B = (unsigned long long)m2 | ((unsigned long long)m3 << 32);
                acc_e += __popcll(A & sme2[it * 2 + 0][lane]);
                acc_e += __popcll(B & sme2[it * 2 + 1][lane]);
            }
        }
    }
    {
        float4 v[4];
#pragma unroll
        for (int q = 0; q < 4; q++) {
            int base = q * 128 + lane * 4;
            v[q] = (base < I_NO) ? *(const float4*)(ri + base)
                                 : make_float4(0.f, 0.f, 0.f, 0.f);
        }
#pragma unroll
        for (int q = 0; q < 4; q++) {
            unsigned m0 = __ballot_sync(0xffffffffu, v[q].x != 0.f);
            unsigned m1 = __ballot_sync(0xffffffffu, v[q].y != 0.f);
            unsigned m2 = __ballot_sync(0xffffffffu, v[q].z != 0.f);
            unsigned m3 = __ballot_sync(0xffffffffu, v[q].w != 0.f);
            if (lane < SUB) {
                unsigned long long A = (unsigned long long)m0 | ((unsigned long long)m1 << 32);
                unsigned long long B = (unsigned long long)m2 | ((unsigned long long)m3 << 32);
                acc_i += __popcll(A & smi2[q * 2 + 0][lane]);
                acc_i += __popcll(B & smi2[q * 2 + 1][lane]);
            }
        }
    }
    if (lane < SUB) {
        g_INe[lane][row] = (float)acc_e;
        g_INi[lane][row] = (float)acc_i;
    }
}

// ---------------- K2: fused causal conv (48 taps) + wavefront recurrence ----------
// Block b covers outputs t in [b*160, b*160+160). syn computed in smem for
// j = t - t0 + 13 in [0,176); IN staged for idx i = t - t0 + 60 in [0,224).
// syn[j] = sum_m kerR[m] * IN[j+m], m in [0,48), kerR[m] = kernel at lag 47-m.
__device__ __forceinline__ float sigm(float x) { return 1.f / (1.f + __expf(-x)); }

__global__ __launch_bounds__(288) void k_fused(const float* __restrict__ Ws_syn,
                                               const float* __restrict__ Wns_syn,
                                               const float* __restrict__ Ds,
                                               const float* __restrict__ Dns,
                                               const float* __restrict__ C_den,
                                               const float* __restrict__ Ths_g,
                                               const float* __restrict__ Thns_g,
                                               const float* __restrict__ Ws_g,
                                               const float* __restrict__ Wns_g,
                                               float* __restrict__ out) {
    // union region: [kers | inb_e | inb_i] during conv, reused as obuf afterwards
    __shared__ __align__(16) char uni[30720];
    float* kers  = (float*)uni;                       // [12][4][48]  9216 B
    float* inb_e = (float*)(uni + 9216);              // [12][224]   10752 B
    float* inb_i = (float*)(uni + 9216 + 10752);      // [12][224]   10752 B
    float* obuf  = (float*)uni;                       // [160][35]   22400 B (aliased)
    __shared__ float sh_ss[SUB][SLEN];
    __shared__ float sh_sn[SUB][SLEN];
    __shared__ float cwns[SUB][SUB], cden[SUB][SUB];
    __shared__ float ths[SUB], thns[SUB], wsub[SUB], wnsub[SUB];

    const int tid = threadIdx.x;
    const int t0 = blockIdx.x * TT;

    if (tid < SUB * SUB) {
        float c = C_den[tid];
        cden[tid / SUB][tid % SUB] = c;
        cwns[tid / SUB][tid % SUB] = c * Wns_g[tid % SUB];
    }
    if (tid < SUB) {
        ths[tid] = Ths_g[tid];
        thns[tid] = Thns_g[tid];
        wsub[tid] = Ws_g[tid];
        wnsub[tid] = Wns_g[tid];
    }

    // --- build reversed kernels: 2304 entries, 8 per thread ---
#pragma unroll
    for (int p = 0; p < 8; p++) {
        int id = tid + p * 288;
        if (id < SUB * 4 * CTAP) {
            int s = id / (4 * CTAP);
            int rem = id % (4 * CTAP);
            int c = rem / CTAP;      // 0:e_s 1:i_s 2:e_ns 3:i_ns
            int m = rem % CTAP;
            int ch = c & 1;
            bool nsk = (c >= 2);
            const float* W = nsk ? Wns_syn : Ws_syn;
            const float* D = nsk ? Dns : Ds;
            float delay = expf(D[s * 2 + ch]);
            float fk = (float)(CTAP - 1 - m);
            float u = fmaxf(fk - delay, 0.f);
            float a = u, b = u * 0.60653065971f, cc = u * 0.36787944117f;
            kers[id] = W[s * 6 + 0 * 2 + ch] * a * expf(-a) +
                       W[s * 6 + 1 * 2 + ch] * b * expf(-b) +
                       W[s * 6 + 2 * 2 + ch] * cc * expf(-cc);
        }
    }

    // --- stage IN tiles: i in [0,224) -> t = t0 - 60 + i ---
    for (int i = tid; i < SUB * INP; i += 288) {
        int s = i / INP, jj = i % INP;
        int g = t0 - 60 + jj;
        bool in = (g >= 0 && g < T_DATA);
        inb_e[i] = in ? g_INe[s][g] : 0.f;
        inb_i[i] = in ? g_INi[s][g] : 0.f;
    }
    __syncthreads();

    // --- conv: 264 threads, thread -> (sub, 8 consecutive syn outputs) ---
    if (tid < SUB * 22) {
        int s = tid / 22, l22 = tid % 22;
        const float4* re4 = (const float4*)(inb_e + s * INP);
        const float4* ri4 = (const float4*)(inb_i + s * INP);
        const float* k0 = kers + s * (4 * CTAP);

        float accs[8] = {0, 0, 0, 0, 0, 0, 0, 0};
        float accn[8] = {0, 0, 0, 0, 0, 0, 0, 0};
        float4 Ae = re4[l22 * 2 + 0], Be = re4[l22 * 2 + 1];
        float4 Ai = ri4[l22 * 2 + 0], Bi = ri4[l22 * 2 + 1];
#pragma unroll
        for (int kb = 0; kb < CTAP; kb += 4) {
            float4 Ce4 = re4[l22 * 2 + kb / 4 + 2];
            float4 Ci4 = ri4[l22 * 2 + kb / 4 + 2];
            float we[12] = {Ae.x, Ae.y, Ae.z, Ae.w, Be.x, Be.y, Be.z, Be.w,
                            Ce4.x, Ce4.y, Ce4.z, Ce4.w};
            float wi[12] = {Ai.x, Ai.y, Ai.z, Ai.w, Bi.x, Bi.y, Bi.z, Bi.w,
                            Ci4.x, Ci4.y, Ci4.z, Ci4.w};
#pragma unroll
            for (int u4 = 0; u4 < 4; u4++) {
                float ces = k0[0 * CTAP + kb + u4];
                float cis = k0[1 * CTAP + kb + u4];
                float cen = k0[2 * CTAP + kb + u4];
                float cin = k0[3 * CTAP + kb + u4];
#pragma unroll
                for (int r = 0; r < 8; r++) {
                    float e = we[u4 + r];
                    float i = wi[u4 + r];
                    accs[r] = fmaf(ces, e, accs[r]);
                    accs[r] = fmaf(cis, i, accs[r]);
                    accn[r] = fmaf(cen, e, accn[r]);
                    accn[r] = fmaf(cin, i, accn[r]);
                }
            }
            Ae = Be; Be = Ce4; Ai = Bi; Bi = Ci4;
        }
        int j0 = l22 * 8;
#pragma unroll
        for (int r = 0; r < 8; r++) {
            sh_ss[s][j0 + r] = accs[r];
            sh_sn[s][j0 + r] = accn[r];
        }
    }
    __syncthreads();   // conv done; kers/inb dead, obuf alias now writable

    // --- recurrence: warps 0..7, lane = t offset with 12-lane halo ---
    const int warp = tid >> 5, lane = tid & 31;
    if (warp < 8) {
        const int t = t0 + warp * 20 + lane - 12;
        const int j = warp * 20 + lane + 1;     // syn index for t
        const bool tin = (t >= 0);
        const bool rec = (t >= 1);

        float sn[SUB], ss[SUB];
#pragma unroll
        for (int q = 0; q < SUB; q++) {
            sn[q] = tin ? sh_sn[q][j] : 0.f;
            ss[q] = tin ? sh_ss[q][j] : 0.f;
        }
        float ssp0 = rec ? sh_ss[0][j - 1] : 0.f;

        float sig[SUB], sigp[SUB];
#pragma unroll
        for (int q = 0; q < SUB; q++) {
            float r = 0.f;
#pragma unroll
            for (int qq = 0; qq < q; qq++) r += cwns[q][qq] * sigp[qq];
            float x = sn[q] + thns[q] + (rec ? r : 0.f);
            sig[q] = sigm(x);
            sigp[q] = __shfl_up_sync(0xffffffffu, sig[q], 1);
        }

        if (lane >= 12) {
            int lt = warp * 20 + lane - 12;
            float* o = obuf + lt * 35;
            o[0] = sigm(ss[0] + ths[0]) * wsub[0];
#pragma unroll
            for (int q = 1; q < SUB; q++) o[q] = sig[q] * wsub[q];
#pragma unroll
            for (int q = 0; q < SUB; q++) o[SUB + q] = sig[q] * wnsub[q];

            float ysp[SUB];
            ysp[0] = rec ? sigm(ssp0 + ths[0]) * wsub[0] : 0.f;
#pragma unroll
            for (int q = 1; q < SUB; q++) ysp[q] = rec ? sigp[q] * wsub[q] : 0.f;
#pragma unroll
            for (int i = 1; i < SUB; i++) {
                float x = ss[i] + ths[i];
#pragma unroll
                for (int qq = 0; qq < i; qq++) x = fmaf(cden[i][qq], ysp[qq], x);
                o[2 * SUB + (i - 1)] = sigm(x);
            }
        }
    }
    __syncthreads();

    // --- coalesced copy out: 160 rows * 35 floats = 1400 float4 ---
    const float4* src = (const float4*)obuf;
    float4* dst = (float4*)(out + (size_t)blockIdx.x * (TT * 35));
    for (int i = tid; i < TT * 35 / 4; i += 288) dst[i] = src[i];
}

// ---------------- launcher ----------------
extern "C" void kernel_launch(void* const* d_in, const int* in_sizes, int n_in,
                              void* d_out, int out_size) {
    const float* S_e      = (const float*)d_in[0];
    const float* S_i      = (const float*)d_in[1];
    const float* C_syn_e  = (const float*)d_in[2];
    const float* C_syn_i  = (const float*)d_in[3];
    const float* C_den    = (const float*)d_in[4];
    const float* W_s_syn  = (const float*)d_in[5];
    const float* W_ns_syn = (const float*)d_in[6];
    const float* Delta_s  = (const float*)d_in[7];
    const float* Delta_ns = (const float*)d_in[8];
    const float* Theta_s  = (const float*)d_in[9];
    const float* Theta_ns = (const float*)d_in[10];
    const float* W_s_sub  = (const float*)d_in[11];
    const float* W_ns_sub = (const float*)d_in[12];
    float* out = (float*)d_out;

    k_pack<<<120, 256>>>(C_syn_e, C_syn_i);
    k_reduce<<<T_DATA / 8, 256>>>(S_e, S_i);
    k_fused<<<T_DATA / TT, 288>>>(W_s_syn, W_ns_syn, Delta_s, Delta_ns,
                                  C_den, Theta_s, Theta_ns, W_s_sub, W_ns_sub, out);
}